// round 13
// baseline (speedup 1.0000x reference)
#include <cuda_runtime.h>
#include <math.h>
#include <stdint.h>

#define SS 64
#define NN 256
#define CC 3
#define BB 64
#define LL 2048
#define WW (LL - SS + 1)   /* 1985 */
#define WPAD 2048
#define NSTAGE 4
#define PAIRS 32           /* shapelet pairs per stage (64 shapelets) */
#define XROW 2112          /* staged x pairs per channel */
#define THREADS 256

typedef unsigned long long ull;

__device__ float g_winsq[BB * CC * WPAD];
__device__ ull   g_shp[NSTAGE * CC * PAIRS * SS];   /* interleaved (n0,n1) pairs */
__device__ float2 g_sqn[NSTAGE * CC * PAIRS];
__constant__ ull c_shp[CC * PAIRS * SS];            /* 49152 B, one stage */

// ---------- packed f32x2 helpers ----------
__device__ __forceinline__ ull pack2(float v) {
    ull r; asm("mov.b64 %0, {%1, %1};" : "=l"(r) : "f"(v)); return r;
}
__device__ __forceinline__ ull packab(float a, float b) {
    ull r; asm("mov.b64 %0, {%1, %2};" : "=l"(r) : "f"(a), "f"(b)); return r;
}
__device__ __forceinline__ void fma2(ull& d, ull a, ull b) {
    asm("fma.rn.f32x2 %0, %1, %2, %0;" : "+l"(d) : "l"(a), "l"(b));
}
__device__ __forceinline__ ull add2(ull a, ull b) {
    ull r; asm("add.rn.f32x2 %0, %1, %2;" : "=l"(r) : "l"(a), "l"(b)); return r;
}
__device__ __forceinline__ void unpack2(float& lo, float& hi, ull v) {
    asm("mov.b64 {%0, %1}, %2;" : "=f"(lo), "=f"(hi) : "l"(v));
}
__device__ __forceinline__ float sqrt_ap(float v) {
    float r; asm("sqrt.approx.f32 %0, %1;" : "=f"(r) : "f"(v)); return r;
}
__device__ __forceinline__ uint32_t smem_u32(const void* p) {
    uint32_t a;
    asm("{ .reg .u64 t; cvta.to.shared.u64 t, %1; cvt.u32.u64 %0, t; }" : "=r"(a) : "l"(p));
    return a;
}

// ---------- kernel 1: window squared norms ----------
__global__ void winsq_kernel(const float* __restrict__ x) {
    int b = blockIdx.x, c = blockIdx.y;
    __shared__ float xs[LL];
    const float* xp = x + (b * CC + c) * LL;
    for (int i = threadIdx.x; i < LL; i += blockDim.x) xs[i] = xp[i];
    __syncthreads();
    for (int w = threadIdx.x; w < WPAD; w += blockDim.x) {
        float s = 0.f;
        if (w < WW) {
#pragma unroll 16
            for (int k = 0; k < SS; k++) { float v = xs[w + k]; s = fmaf(v, v, s); }
        }
        g_winsq[(b * CC + c) * WPAD + w] = s;
    }
}

// ---------- kernel 2: shapelet pair interleave + norms ----------
__global__ void shp_prep(const float* __restrict__ shp) {
    int st = blockIdx.x, c = blockIdx.y;
    for (int i = threadIdx.x; i < PAIRS * SS; i += blockDim.x) {
        int p = i >> 6, s = i & 63;
        int n0 = st * 64 + 2 * p;
        float a = shp[(c * NN + n0) * SS + s];
        float b = shp[(c * NN + n0 + 1) * SS + s];
        ((float2*)g_shp)[(st * CC + c) * (PAIRS * SS) + i] = make_float2(a, b);
    }
    if (threadIdx.x < PAIRS) {
        int p = threadIdx.x;
        int n0 = st * 64 + 2 * p;
        float s0 = 0.f, s1 = 0.f;
#pragma unroll 8
        for (int s = 0; s < SS; s++) {
            float a = shp[(c * NN + n0) * SS + s];
            float b = shp[(c * NN + n0 + 1) * SS + s];
            s0 = fmaf(a, a, s0); s1 = fmaf(b, b, s1);
        }
        g_sqn[(st * CC + c) * PAIRS + p] = make_float2(s0, s1);
    }
}

// ---------- kernel 3: main (one shapelet pair per block) ----------
__global__ __launch_bounds__(THREADS, 3) void main_kernel(
    const float* __restrict__ x, float* __restrict__ out, int stage)
{
    extern __shared__ float2 xs[];   /* CC * XROW duplicated pairs, 50688 B */
    __shared__ float rmin[8][2];

    const int pair = blockIdx.x;     // 0..31
    const int b    = blockIdx.y;     // 0..63
    const int tid  = threadIdx.x;
    const int lane = tid & 31;
    const int wk   = tid >> 5;       // warp -> 256-w slice

    // Stage x rows as duplicated pairs (clamped tail)
    for (int c = 0; c < CC; c++) {
        const float* xp = x + (b * CC + c) * LL;
        for (int k = tid; k < XROW; k += THREADS) {
            float v = xp[min(k, LL - 1)];
            xs[c * XROW + k] = make_float2(v, v);
        }
    }
    __syncthreads();

    const uint32_t xs_base = smem_u32(xs);
    const int wr = 256 * wk + 2 * lane;     // w = wr + 64*j + e
    const ull NEG2 = pack2(-2.0f);
    const float INF = __int_as_float(0x7f800000);

    float t0[8], t1[8];
#pragma unroll
    for (int s = 0; s < 8; s++) { t0[s] = 0.f; t1[s] = 0.f; }

#pragma unroll 1
    for (int c = 0; c < CC; c++) {
        const uint32_t xaddr = xs_base + (uint32_t)(c * XROW + wr) * 8u;
        const ull* shrow = &c_shp[(c * PAIRS + pair) * SS];

        ull acc[8];
#pragma unroll
        for (int s = 0; s < 8; s++) acc[s] = 0ull;
        ull shA = 0ull;

#pragma unroll
        for (int jb = 0; jb < 4; jb++) {
#pragma unroll
            for (int i = 0; i < 32; i++) {
                ull x0, x1;
                asm("ld.shared.v2.u64 {%0,%1}, [%2];"
                    : "=l"(x0), "=l"(x1)
                    : "r"(xaddr + (uint32_t)((jb * 64 + 2 * i) * 8)));
                ulonglong2 shv = *(const ulonglong2*)(shrow + 2 * i);
                // interior: w slots 2jb (e=0), 2jb+1 (e=1)
                fma2(acc[2 * jb],     x0, shv.x);   // (e0, s0)
                fma2(acc[2 * jb],     x1, shv.y);   // (e0, s0+1)
                fma2(acc[2 * jb + 1], x1, shv.x);   // (e1, s0)
                if (jb > 0 || i > 0) {
                    // (e1, s0-1): same jb when i>0; previous jb's s=63 when i==0
                    fma2(acc[i > 0 ? 2 * jb + 1 : 2 * jb - 1], x0, shA);
                }
                shA = shv.y;
            }
        }
        {   // tail: u = wr+256 feeds (e1, j=3, s=63)
            ull x0;
            asm("ld.shared.u64 %0, [%1];"
                : "=l"(x0) : "r"(xaddr + (uint32_t)(256 * 8)));
            fma2(acc[7], x0, shA);
        }

        // epilogue: d = sqrt(max(ws + sqn - 2*cross, 0)), accumulate over c
        float2 qn = g_sqn[(stage * CC + c) * PAIRS + pair];
        ull sqn2 = packab(qn.x, qn.y);
        const float* wsrow = g_winsq + (b * CC + c) * WPAD;
#pragma unroll
        for (int s = 0; s < 8; s++) {
            int w = wr + 64 * (s >> 1) + (s & 1);
            ull base = add2(pack2(wsrow[w]), sqn2);
            fma2(base, acc[s], NEG2);
            float lo, hi;
            unpack2(lo, hi, base);
            t0[s] += sqrt_ap(fmaxf(lo, 0.f));
            t1[s] += sqrt_ap(fmaxf(hi, 0.f));
        }
    }

    // thread-local min with W mask
    float m0 = INF, m1 = INF;
#pragma unroll
    for (int s = 0; s < 8; s++) {
        int w = wr + 64 * (s >> 1) + (s & 1);
        if (w < WW) { m0 = fminf(m0, t0[s]); m1 = fminf(m1, t1[s]); }
    }
    // warp butterfly over 32 lanes
#pragma unroll
    for (int o = 1; o < 32; o <<= 1) {
        m0 = fminf(m0, __shfl_xor_sync(0xffffffffu, m0, o));
        m1 = fminf(m1, __shfl_xor_sync(0xffffffffu, m1, o));
    }
    if (lane == 0) { rmin[wk][0] = m0; rmin[wk][1] = m1; }
    __syncthreads();
    if (tid < 2) {
        float m = rmin[0][tid];
#pragma unroll
        for (int wq = 1; wq < 8; wq++) m = fminf(m, rmin[wq][tid]);
        out[b * NN + stage * 64 + 2 * pair + tid] = m;
    }
}

extern "C" void kernel_launch(void* const* d_in, const int* in_sizes, int n_in,
                              void* d_out, int out_size) {
    (void)in_sizes; (void)n_in; (void)out_size;
    const float* x   = (const float*)d_in[0];
    const float* shp = (const float*)d_in[1];
    float* out = (float*)d_out;

    const int smem_bytes = CC * XROW * (int)sizeof(float2);
    cudaFuncSetAttribute(main_kernel, cudaFuncAttributeMaxDynamicSharedMemorySize, smem_bytes);

    winsq_kernel<<<dim3(BB, CC), 256>>>(x);
    shp_prep<<<dim3(NSTAGE, CC), 256>>>(shp);

    void* gshp_ptr = nullptr;
    cudaGetSymbolAddress(&gshp_ptr, g_shp);
    const size_t stage_bytes = (size_t)CC * PAIRS * SS * sizeof(ull);  // 49152

    for (int st = 0; st < NSTAGE; st++) {
        cudaMemcpyToSymbolAsync(c_shp,
                                (const char*)gshp_ptr + (size_t)st * stage_bytes,
                                stage_bytes, 0, cudaMemcpyDeviceToDevice, 0);
        main_kernel<<<dim3(PAIRS, BB), THREADS, smem_bytes>>>(x, out, st);
    }
}

// round 14
// speedup vs baseline: 3.3185x; 3.3185x over previous
#include <cuda_runtime.h>
#include <math.h>
#include <stdint.h>

#define SS 64
#define NN 256
#define CC 3
#define BB 64
#define LL 2048
#define WW (LL - SS + 1)   /* 1985 */
#define WPAD 2048
#define NT 32              /* shapelets per block */
#define NPAIR 16
#define WG 16              /* w-groups (threads dim) */
#define WPT 8              /* w per thread per chunk */
#define WSLICE 8           /* w slices (blockIdx.z) */
#define WPB 256            /* w per block */
#define CHUNKS 2           /* 2 x 128 w per block */
#define XS 320             /* staged x values per channel */
#define THREADS 256

typedef unsigned long long ull;

__device__ float g_winsq[BB * CC * WPAD];

// ---------- packed f32x2 helpers (sm_103a fma pipe, 2x fp32 throughput) ----------
__device__ __forceinline__ ull pack2(float v) {
    ull r; asm("mov.b64 %0, {%1, %1};" : "=l"(r) : "f"(v)); return r;
}
__device__ __forceinline__ void fma2(ull& d, ull a, ull b) {
    asm("fma.rn.f32x2 %0, %1, %2, %0;" : "+l"(d) : "l"(a), "l"(b));
}
__device__ __forceinline__ ull add2(ull a, ull b) {
    ull r; asm("add.rn.f32x2 %0, %1, %2;" : "=l"(r) : "l"(a), "l"(b)); return r;
}
__device__ __forceinline__ void unpack2(float& lo, float& hi, ull v) {
    asm("mov.b64 {%0, %1}, %2;" : "=f"(lo), "=f"(hi) : "l"(v));
}
__device__ __forceinline__ float sqrt_ap(float v) {
    float r; asm("sqrt.approx.f32 %0, %1;" : "=f"(r) : "f"(v)); return r;
}

// ---------- kernel 1: window squared norms + output init (fused) ----------
__global__ void winsq_kernel(const float* __restrict__ x, float* __restrict__ out) {
    int b = blockIdx.x, c = blockIdx.y;
    __shared__ float xs[LL];
    const float* xp = x + (b * CC + c) * LL;
    for (int i = threadIdx.x; i < LL; i += blockDim.x) xs[i] = xp[i];
    if (c == 0)
        out[b * 256 + threadIdx.x] = __int_as_float(0x7f800000);
    __syncthreads();
    for (int w = threadIdx.x; w < WPAD; w += blockDim.x) {
        float s = 0.f;
        if (w < WW) {
#pragma unroll 16
            for (int k = 0; k < SS; k++) { float v = xs[w + k]; s = fmaf(v, v, s); }
        }
        g_winsq[(b * CC + c) * WPAD + w] = s;
    }
}

// ---------- kernel 2: main ----------
__global__ __launch_bounds__(THREADS, 3) void main_kernel(
    const float* __restrict__ x, const float* __restrict__ shp,
    float* __restrict__ out)
{
    extern __shared__ __align__(16) unsigned char smem_raw[];
    float2* xd   = (float2*)smem_raw;                 // CC*XS duplicated pairs (7680 B)
    float2* shs2 = xd + CC * XS;                      // CC*NPAIR*65 (24960 B)
    float2* wsd  = shs2 + CC * NPAIR * 65;            // CC*WPB duplicated pairs (6144 B)
    float2* sqs2 = wsd + CC * WPB;                    // CC*NPAIR (384 B)
    __shared__ float red[8][NPAIR][2];

    const int ntile = blockIdx.x;      // 0..7
    const int b     = blockIdx.y;      // 0..63
    const int wsl   = blockIdx.z;      // 0..7
    const int tid   = threadIdx.x;
    const int npair = tid & (NPAIR - 1);
    const int wg    = tid >> 4;        // 0..15
    const int warp  = tid >> 5;
    const int lane  = tid & 31;
    const int wbase = wsl * WPB;

    // Stage x window as duplicated pairs (clamped)
    for (int i = tid; i < CC * XS; i += THREADS) {
        int c = i / XS, j = i - c * XS;
        float v = x[(b * CC + c) * LL + min(wbase + j, LL - 1)];
        xd[i] = make_float2(v, v);
    }
    // Stage shapelet tile, n-pair interleaved, pad 65
    for (int i = tid; i < CC * NPAIR * SS; i += THREADS) {
        int c = i / (NPAIR * SS);
        int r = i - c * (NPAIR * SS);
        int p = r / SS, s = r - p * SS;
        int n0 = ntile * NT + 2 * p;
        float2 v;
        v.x = shp[(c * NN + n0) * SS + s];
        v.y = shp[(c * NN + n0 + 1) * SS + s];
        shs2[(c * NPAIR + p) * 65 + s] = v;
    }
    // Zero the pad element (read by sh double-buffer prefetch, never used)
    if (tid < CC * NPAIR)
        shs2[tid * 65 + SS] = make_float2(0.f, 0.f);
    // Stage winsq slice as duplicated pairs
    for (int i = tid; i < CC * WPB; i += THREADS) {
        int c = i >> 8, j = i & 255;
        float v = g_winsq[(b * CC + c) * WPAD + wbase + j];
        wsd[i] = make_float2(v, v);
    }
    __syncthreads();

    // Shapelet squared norms per pair
    if (tid < CC * NPAIR) {
        int c = tid / NPAIR, p = tid - c * NPAIR;
        float a0 = 0.f, a1 = 0.f;
#pragma unroll 8
        for (int s = 0; s < SS; s++) {
            float2 v = shs2[(c * NPAIR + p) * 65 + s];
            a0 = fmaf(v.x, v.x, a0);
            a1 = fmaf(v.y, v.y, a1);
        }
        sqs2[tid] = make_float2(a0, a1);
    }
    __syncthreads();

    ull sqn2[CC];
#pragma unroll
    for (int c = 0; c < CC; c++) {
        float2 q = sqs2[c * NPAIR + npair];
        ull r;
        asm("mov.b64 %0, {%1, %2};" : "=l"(r) : "f"(q.x), "f"(q.y));
        sqn2[c] = r;
    }
    const ull NEG2 = pack2(-2.0f);
    const float INF = __int_as_float(0x7f800000);
    float tmin0 = INF, tmin1 = INF;

#pragma unroll
    for (int chunk = 0; chunk < CHUNKS; chunk++) {
        const int w0l = chunk * (WG * WPT) + wg * WPT;   // local w, 0..248

        float t0[WPT], t1[WPT];
#pragma unroll
        for (int j = 0; j < WPT; j++) { t0[j] = 0.f; t1[j] = 0.f; }

#pragma unroll
        for (int c = 0; c < CC; c++) {
            const ull* xr =
                (const ull*)(xd + c * XS + w0l);
            const ull* shrow =
                (const ull*)(shs2 + (c * NPAIR + npair) * 65);

            ull acc2[WPT];
#pragma unroll
            for (int j = 0; j < WPT; j++) acc2[j] = 0ull;

            // rolling packed window of 8 duplicated x pairs
            ull xw2[8];
#pragma unroll
            for (int k = 0; k < 8; k++) xw2[k] = xr[k];

            // software-pipelined: sh double-buffered, x refilled early
            ull sh_cur = shrow[0];
            for (int sb = 0; sb < SS; sb += 8) {
#pragma unroll
                for (int u = 0; u < 8; u++) {
                    const int s = sb + u;
                    ull sh_nxt = shrow[s + 1];          // pad row => in-bounds at s=63
                    fma2(acc2[0], xw2[u], sh_cur);      // j=0: only reader of slot u
                    ull xnew = xr[s + 8];               // refill issued early
#pragma unroll
                    for (int j = 1; j < WPT; j++)
                        fma2(acc2[j], xw2[(u + j) & 7], sh_cur);
                    xw2[u] = xnew;
                    sh_cur = sh_nxt;
                }
            }

            // epilogue: d2 = ws + sqn - 2*cross (ws already duplicated in smem)
            const ull* wsrow =
                (const ull*)(wsd + c * WPB + w0l);
#pragma unroll
            for (int j = 0; j < WPT; j++) {
                ull base = add2(wsrow[j], sqn2[c]);
                fma2(base, acc2[j], NEG2);
                float lo, hi;
                unpack2(lo, hi, base);
                t0[j] += sqrt_ap(fmaxf(lo, 0.f));
                t1[j] += sqrt_ap(fmaxf(hi, 0.f));
            }
        }

#pragma unroll
        for (int j = 0; j < WPT; j++) {
            if (wbase + w0l + j < WW) {
                tmin0 = fminf(tmin0, t0[j]);
                tmin1 = fminf(tmin1, t1[j]);
            }
        }
    }

    // reduce across 16 w-groups: lane bit 4, then cross-warp via smem
    tmin0 = fminf(tmin0, __shfl_xor_sync(0xffffffffu, tmin0, 16));
    tmin1 = fminf(tmin1, __shfl_xor_sync(0xffffffffu, tmin1, 16));
    if (lane < NPAIR) {
        red[warp][lane][0] = tmin0;
        red[warp][lane][1] = tmin1;
    }
    __syncthreads();
    if (tid < NPAIR) {
        float m0 = red[0][tid][0], m1 = red[0][tid][1];
#pragma unroll
        for (int wr = 1; wr < 8; wr++) {
            m0 = fminf(m0, red[wr][tid][0]);
            m1 = fminf(m1, red[wr][tid][1]);
        }
        unsigned int* ob = (unsigned int*)(out + b * NN + ntile * NT + 2 * tid);
        atomicMin(ob,     __float_as_uint(m0));
        atomicMin(ob + 1, __float_as_uint(m1));
    }
}

extern "C" void kernel_launch(void* const* d_in, const int* in_sizes, int n_in,
                              void* d_out, int out_size) {
    (void)in_sizes; (void)n_in; (void)out_size;
    const float* x   = (const float*)d_in[0];
    const float* shp = (const float*)d_in[1];
    float* out = (float*)d_out;

    const int smem_bytes = CC * XS * 8 + CC * NPAIR * 65 * 8 + CC * WPB * 8 + CC * NPAIR * 8;
    cudaFuncSetAttribute(main_kernel, cudaFuncAttributeMaxDynamicSharedMemorySize, smem_bytes);

    winsq_kernel<<<dim3(BB, CC), 256>>>(x, out);
    main_kernel<<<dim3(NN / NT, BB, WSLICE), THREADS, smem_bytes>>>(x, shp, out);
}

// round 15
// speedup vs baseline: 4.5405x; 1.3682x over previous
#include <cuda_runtime.h>
#include <cuda_bf16.h>
#include <math.h>
#include <stdint.h>

#define SS 64
#define NN 256
#define CC 3
#define BB 64
#define LL 2048
#define WW (LL - SS + 1)   /* 1985 */
#define WPAD 2048
#define THREADS 256

typedef uint32_t u32;

__device__ float g_winsq[BB * CC * WPAD];
__device__ __nv_bfloat16 g_shpbf[CC * NN * 128];   /* [c][n][hi0..63 | lo0..63] */
__device__ float g_shpsq[CC * NN];

/* ---- smem layout (bytes) ---- */
#define SM_SH   0          /* 192 rows x 272B (bf16[128] + 8 pad)  = 52224 */
#define SM_X    52224      /* xe_hi|xo_hi|xe_lo|xo_lo, each 3*192 bf16 = 1152B; total 4608 */
#define SM_WS   56832      /* 3*128 f32 = 1536 */
#define SM_SQ   58368      /* 3*64 f32 = 768 */
#define SM_MIN  59136      /* 64 f32 = 256 */
#define SM_TOTAL 59392

__device__ __forceinline__ float sqrt_ap(float v) {
    float r; asm("sqrt.approx.f32 %0, %1;" : "=f"(r) : "f"(v)); return r;
}

__device__ __forceinline__ void mma16816(
    float& d0, float& d1, float& d2, float& d3,
    u32 a0, u32 a1, u32 a2, u32 a3, u32 b0, u32 b1)
{
    asm("mma.sync.aligned.m16n8k16.row.col.f32.bf16.bf16.f32 "
        "{%0,%1,%2,%3}, {%4,%5,%6,%7}, {%8,%9}, {%0,%1,%2,%3};"
        : "+f"(d0), "+f"(d1), "+f"(d2), "+f"(d3)
        : "r"(a0), "r"(a1), "r"(a2), "r"(a3), "r"(b0), "r"(b1));
}

/* ---------- kernel 1: window squared norms + output init ---------- */
__global__ void winsq_kernel(const float* __restrict__ x, float* __restrict__ out) {
    int b = blockIdx.x, c = blockIdx.y;
    __shared__ float xs[LL];
    const float* xp = x + (b * CC + c) * LL;
    for (int i = threadIdx.x; i < LL; i += blockDim.x) xs[i] = xp[i];
    if (c == 0)
        out[b * 256 + threadIdx.x] = __int_as_float(0x7f800000);
    __syncthreads();
    for (int w = threadIdx.x; w < WPAD; w += blockDim.x) {
        float s = 0.f;
        if (w < WW) {
#pragma unroll 16
            for (int k = 0; k < SS; k++) { float v = xs[w + k]; s = fmaf(v, v, s); }
        }
        g_winsq[(b * CC + c) * WPAD + w] = s;
    }
}

/* ---------- kernel 2: shapelet bf16 split + norms ---------- */
__global__ void shp_prep(const float* __restrict__ shp) {
    int c = blockIdx.x, n = threadIdx.x;
    const float* p = shp + (c * NN + n) * SS;
    __nv_bfloat16* dst = g_shpbf + (c * NN + n) * 128;
    float sq = 0.f;
#pragma unroll 8
    for (int s = 0; s < SS; s++) {
        float v = p[s];
        sq = fmaf(v, v, sq);
        __nv_bfloat16 hi = __float2bfloat16(v);
        __nv_bfloat16 lo = __float2bfloat16(v - __bfloat162float(hi));
        dst[s] = hi;
        dst[64 + s] = lo;
    }
    g_shpsq[c * NN + n] = sq;
}

/* ---------- kernel 3: main (tensor) ---------- */
__global__ __launch_bounds__(THREADS, 2) void main_kernel(
    const float* __restrict__ x, float* __restrict__ out)
{
    extern __shared__ __align__(16) unsigned char smem[];
    float* wsS = (float*)(smem + SM_WS);
    float* sqS = (float*)(smem + SM_SQ);
    float* mnS = (float*)(smem + SM_MIN);

    const int wsl = blockIdx.x;          // 0..15
    const int nsl = blockIdx.y;          // 0..3
    const int b   = blockIdx.z;          // 0..63
    const int tid = threadIdx.x;
    const int warp = tid >> 5, lane = tid & 31;
    const int g = lane >> 2, t = lane & 3;
    const int w0 = wsl * 128;
    const int n0 = nsl * 64;

    /* ---- stage shapelet tile: 192 rows x 64 u32, padded rows ---- */
    {
        const u32* src = (const u32*)g_shpbf;
        for (int i = tid; i < 192 * 64; i += THREADS) {
            int row = i >> 6, k2 = i & 63;
            int c = row >> 6, nl = row & 63;
            u32 v = src[((c * NN) + n0 + nl) * 64 + k2];
            *(u32*)(smem + SM_SH + row * 272 + k2 * 4) = v;
        }
    }
    /* ---- stage x window (192 per c) into 4 shifted bf16 arrays ---- */
    {
        __nv_bfloat16* xe_hi = (__nv_bfloat16*)(smem + SM_X);
        __nv_bfloat16* xo_hi = xe_hi + 576;
        __nv_bfloat16* xe_lo = xo_hi + 576;
        __nv_bfloat16* xo_lo = xe_lo + 576;
        for (int i = tid; i < CC * 192; i += THREADS) {
            int c = i / 192, j = i - c * 192;
            float v = x[(b * CC + c) * LL + min(w0 + j, LL - 1)];
            __nv_bfloat16 hi = __float2bfloat16(v);
            __nv_bfloat16 lo = __float2bfloat16(v - __bfloat162float(hi));
            xe_hi[i] = hi; xe_lo[i] = lo;
            if (j) { xo_hi[i - 1] = hi; xo_lo[i - 1] = lo; }
        }
    }
    /* ---- stage winsq + shp norms + init minbuf ---- */
    for (int i = tid; i < CC * 128; i += THREADS) {
        int c = i >> 7, lw = i & 127;
        wsS[i] = g_winsq[(b * CC + c) * WPAD + w0 + lw];
    }
    for (int i = tid; i < CC * 64; i += THREADS) {
        int c = i >> 6, nl = i & 63;
        sqS[i] = g_shpsq[c * NN + n0 + nl];
    }
    if (tid < 64) mnS[tid] = __int_as_float(0x7f800000);
    __syncthreads();

    /* ---- A pointer: Toeplitz loads; parity of g picks xe vs xo copy ---- */
    const int idx0 = warp * 16 + g + 2 * t;
    const unsigned xb = (g & 1)
        ? (unsigned)(SM_X + 1152 + (idx0 - 1) * 2)
        : (unsigned)(SM_X + idx0 * 2);

    float Dsum[8][4];
#pragma unroll
    for (int nt = 0; nt < 8; nt++)
#pragma unroll
        for (int e = 0; e < 4; e++) Dsum[nt][e] = 0.f;

#pragma unroll 1
    for (int c = 0; c < CC; c++) {
        /* A fragments: 9 regs cover 4 chained k-tiles (a1==a2 by Toeplitz) */
        u32 ah[9], al[9];
        const unsigned char* hp = smem + xb + c * 384;
#pragma unroll
        for (int i = 0; i < 9; i++) {
            ah[i] = *(const u32*)(hp + 16 * i);
            al[i] = *(const u32*)(hp + 2304 + 16 * i);
        }
        const float ws0 = wsS[c * 128 + warp * 16 + g];
        const float ws1 = wsS[c * 128 + warp * 16 + g + 8];

#pragma unroll
        for (int nt = 0; nt < 8; nt++) {
            const unsigned char* bp =
                smem + SM_SH + (unsigned)((c * 64 + nt * 8 + g) * 272 + 4 * t);
            u32 bh[8], bl[8];
#pragma unroll
            for (int i = 0; i < 8; i++) {
                bh[i] = *(const u32*)(bp + 16 * i);
                bl[i] = *(const u32*)(bp + 128 + 16 * i);
            }
            float d0 = 0.f, d1 = 0.f, d2 = 0.f, d3 = 0.f;
#pragma unroll
            for (int k = 0; k < 4; k++) {
                mma16816(d0, d1, d2, d3, ah[2*k], ah[2*k+1], ah[2*k+1], ah[2*k+2],
                         bh[2*k], bh[2*k+1]);
                mma16816(d0, d1, d2, d3, ah[2*k], ah[2*k+1], ah[2*k+1], ah[2*k+2],
                         bl[2*k], bl[2*k+1]);
                mma16816(d0, d1, d2, d3, al[2*k], al[2*k+1], al[2*k+1], al[2*k+2],
                         bh[2*k], bh[2*k+1]);
            }
            float2 q = *(const float2*)(sqS + c * 64 + nt * 8 + 2 * t);
            Dsum[nt][0] += sqrt_ap(fmaxf(fmaf(-2.f, d0, ws0 + q.x), 0.f));
            Dsum[nt][1] += sqrt_ap(fmaxf(fmaf(-2.f, d1, ws0 + q.y), 0.f));
            Dsum[nt][2] += sqrt_ap(fmaxf(fmaf(-2.f, d2, ws1 + q.x), 0.f));
            Dsum[nt][3] += sqrt_ap(fmaxf(fmaf(-2.f, d3, ws1 + q.y), 0.f));
        }
    }

    /* ---- min over w: mask invalid rows, reduce over g-lanes, smem atomicMin ---- */
    const float INF = __int_as_float(0x7f800000);
    const bool v0 = (w0 + warp * 16 + g) < WW;
    const bool v8 = (w0 + warp * 16 + g + 8) < WW;
#pragma unroll
    for (int nt = 0; nt < 8; nt++) {
        float m0 = fminf(v0 ? Dsum[nt][0] : INF, v8 ? Dsum[nt][2] : INF);
        float m1 = fminf(v0 ? Dsum[nt][1] : INF, v8 ? Dsum[nt][3] : INF);
#pragma unroll
        for (int msk = 4; msk < 32; msk <<= 1) {
            m0 = fminf(m0, __shfl_xor_sync(0xffffffffu, m0, msk));
            m1 = fminf(m1, __shfl_xor_sync(0xffffffffu, m1, msk));
        }
        if (lane < 4) {
            atomicMin((u32*)&mnS[nt * 8 + 2 * lane],     __float_as_uint(m0));
            atomicMin((u32*)&mnS[nt * 8 + 2 * lane + 1], __float_as_uint(m1));
        }
    }
    __syncthreads();
    if (tid < 64)
        atomicMin((u32*)&out[b * NN + n0 + tid], __float_as_uint(mnS[tid]));
}

extern "C" void kernel_launch(void* const* d_in, const int* in_sizes, int n_in,
                              void* d_out, int out_size) {
    (void)in_sizes; (void)n_in; (void)out_size;
    const float* x   = (const float*)d_in[0];
    const float* shp = (const float*)d_in[1];
    float* out = (float*)d_out;

    cudaFuncSetAttribute(main_kernel, cudaFuncAttributeMaxDynamicSharedMemorySize, SM_TOTAL);

    winsq_kernel<<<dim3(BB, CC), 256>>>(x, out);
    shp_prep<<<CC, NN>>>(shp);
    main_kernel<<<dim3(16, 4, BB), THREADS, SM_TOTAL>>>(x, out);
}

// round 16
// speedup vs baseline: 8.0427x; 1.7713x over previous
#include <cuda_runtime.h>
#include <cuda_bf16.h>
#include <math.h>
#include <stdint.h>

#define SS 64
#define NN 256
#define CC 3
#define BB 64
#define LL 2048
#define WW (LL - SS + 1)   /* 1985 */
#define WPAD 2048
#define THREADS 256

typedef uint32_t u32;

__device__ float g_winsq[BB * CC * WPAD];
__device__ __nv_bfloat16 g_shpbf[CC * NN * 64];   /* [c][n][s] bf16 */
__device__ float g_shpsq[CC * NN];

/* ---- smem layout (bytes) ---- */
#define SM_SH   0          /* 192 rows x 144B (64 bf16 + 16 pad) = 27648 */
#define SM_X    27648      /* xe_hi | xo_hi, each 3*192 bf16 = 1152B; total 2304 */
#define SM_WS   29952      /* 3*128 f32 = 1536 */
#define SM_SQ   31488      /* 3*64 f32 = 768 */
#define SM_MIN  32256      /* 64 f32 = 256 */
#define SM_TOTAL 32512

__device__ __forceinline__ float sqrt_ap(float v) {
    float r; asm("sqrt.approx.f32 %0, %1;" : "=f"(r) : "f"(v)); return r;
}

__device__ __forceinline__ void mma16816(
    float& d0, float& d1, float& d2, float& d3,
    u32 a0, u32 a1, u32 a2, u32 a3, u32 b0, u32 b1)
{
    asm("mma.sync.aligned.m16n8k16.row.col.f32.bf16.bf16.f32 "
        "{%0,%1,%2,%3}, {%4,%5,%6,%7}, {%8,%9}, {%0,%1,%2,%3};"
        : "+f"(d0), "+f"(d1), "+f"(d2), "+f"(d3)
        : "r"(a0), "r"(a1), "r"(a2), "r"(a3), "r"(b0), "r"(b1));
}

/* ---------- kernel 1: window squared norms + output init ---------- */
__global__ void winsq_kernel(const float* __restrict__ x, float* __restrict__ out) {
    int b = blockIdx.x, c = blockIdx.y;
    __shared__ float xs[LL];
    const float* xp = x + (b * CC + c) * LL;
    for (int i = threadIdx.x; i < LL; i += blockDim.x) xs[i] = xp[i];
    if (c == 0)
        out[b * 256 + threadIdx.x] = __int_as_float(0x7f800000);
    __syncthreads();
    for (int w = threadIdx.x; w < WPAD; w += blockDim.x) {
        float s = 0.f;
        if (w < WW) {
#pragma unroll 16
            for (int k = 0; k < SS; k++) { float v = xs[w + k]; s = fmaf(v, v, s); }
        }
        g_winsq[(b * CC + c) * WPAD + w] = s;
    }
}

/* ---------- kernel 2: shapelet bf16 + norms ---------- */
__global__ void shp_prep(const float* __restrict__ shp) {
    int c = blockIdx.x, n = threadIdx.x;
    const float* p = shp + (c * NN + n) * SS;
    __nv_bfloat16* dst = g_shpbf + (c * NN + n) * 64;
    float sq = 0.f;
#pragma unroll 8
    for (int s = 0; s < SS; s++) {
        float v = p[s];
        sq = fmaf(v, v, sq);
        dst[s] = __float2bfloat16(v);
    }
    g_shpsq[c * NN + n] = sq;
}

/* ---------- kernel 3: main (tensor, pure bf16) ---------- */
__global__ __launch_bounds__(THREADS, 3) void main_kernel(
    const float* __restrict__ x, float* __restrict__ out)
{
    extern __shared__ __align__(16) unsigned char smem[];
    float* wsS = (float*)(smem + SM_WS);
    float* sqS = (float*)(smem + SM_SQ);
    float* mnS = (float*)(smem + SM_MIN);

    const int wsl = blockIdx.x;          // 0..15
    const int nsl = blockIdx.y;          // 0..3
    const int b   = blockIdx.z;          // 0..63
    const int tid = threadIdx.x;
    const int warp = tid >> 5, lane = tid & 31;
    const int g = lane >> 2, t = lane & 3;
    const int w0 = wsl * 128;
    const int n0 = nsl * 64;

    /* ---- stage shapelet tile: 192 rows x 32 u32, padded rows (stride 144B) ---- */
    {
        const u32* src = (const u32*)g_shpbf;
        for (int i = tid; i < 192 * 32; i += THREADS) {
            int row = i >> 5, k2 = i & 31;
            int c = row >> 6, nl = row & 63;
            u32 v = src[((c * NN) + n0 + nl) * 32 + k2];
            *(u32*)(smem + SM_SH + row * 144 + k2 * 4) = v;
        }
    }
    /* ---- stage x window (192 per c) into 2 shifted bf16 arrays ---- */
    {
        __nv_bfloat16* xe_hi = (__nv_bfloat16*)(smem + SM_X);
        __nv_bfloat16* xo_hi = xe_hi + 576;
        for (int i = tid; i < CC * 192; i += THREADS) {
            int c = i / 192, j = i - c * 192;
            float v = x[(b * CC + c) * LL + min(w0 + j, LL - 1)];
            __nv_bfloat16 hi = __float2bfloat16(v);
            xe_hi[i] = hi;
            if (j) xo_hi[i - 1] = hi;
        }
    }
    /* ---- stage winsq + shp norms + init minbuf ---- */
    for (int i = tid; i < CC * 128; i += THREADS) {
        int c = i >> 7, lw = i & 127;
        wsS[i] = g_winsq[(b * CC + c) * WPAD + w0 + lw];
    }
    for (int i = tid; i < CC * 64; i += THREADS) {
        int c = i >> 6, nl = i & 63;
        sqS[i] = g_shpsq[c * NN + n0 + nl];
    }
    if (tid < 64) mnS[tid] = __int_as_float(0x7f800000);
    __syncthreads();

    /* ---- A pointer: Toeplitz loads; parity of g picks xe vs xo copy ---- */
    const int idx0 = warp * 16 + g + 2 * t;
    const unsigned xb = (g & 1)
        ? (unsigned)(SM_X + 1152 + (idx0 - 1) * 2)
        : (unsigned)(SM_X + idx0 * 2);

    float Dsum[8][4];
#pragma unroll
    for (int nt = 0; nt < 8; nt++)
#pragma unroll
        for (int e = 0; e < 4; e++) Dsum[nt][e] = 0.f;

#pragma unroll 1
    for (int c = 0; c < CC; c++) {
        /* A fragments: 9 regs cover 4 chained k-tiles (a1==a2 by Toeplitz) */
        u32 ah[9];
        const unsigned char* hp = smem + xb + c * 384;
#pragma unroll
        for (int i = 0; i < 9; i++)
            ah[i] = *(const u32*)(hp + 16 * i);
        const float ws0 = wsS[c * 128 + warp * 16 + g];
        const float ws1 = wsS[c * 128 + warp * 16 + g + 8];

#pragma unroll
        for (int nt = 0; nt < 8; nt++) {
            const unsigned char* bp =
                smem + SM_SH + (unsigned)((c * 64 + nt * 8 + g) * 144 + 4 * t);
            u32 bh[8];
#pragma unroll
            for (int i = 0; i < 8; i++)
                bh[i] = *(const u32*)(bp + 16 * i);
            float d0 = 0.f, d1 = 0.f, d2 = 0.f, d3 = 0.f;
#pragma unroll
            for (int k = 0; k < 4; k++)
                mma16816(d0, d1, d2, d3, ah[2*k], ah[2*k+1], ah[2*k+1], ah[2*k+2],
                         bh[2*k], bh[2*k+1]);
            float2 q = *(const float2*)(sqS + c * 64 + nt * 8 + 2 * t);
            Dsum[nt][0] += sqrt_ap(fmaxf(fmaf(-2.f, d0, ws0 + q.x), 0.f));
            Dsum[nt][1] += sqrt_ap(fmaxf(fmaf(-2.f, d1, ws0 + q.y), 0.f));
            Dsum[nt][2] += sqrt_ap(fmaxf(fmaf(-2.f, d2, ws1 + q.x), 0.f));
            Dsum[nt][3] += sqrt_ap(fmaxf(fmaf(-2.f, d3, ws1 + q.y), 0.f));
        }
    }

    /* ---- min over w: mask invalid rows, reduce over g-lanes, smem atomicMin ---- */
    const float INF = __int_as_float(0x7f800000);
    const bool v0 = (w0 + warp * 16 + g) < WW;
    const bool v8 = (w0 + warp * 16 + g + 8) < WW;
#pragma unroll
    for (int nt = 0; nt < 8; nt++) {
        float m0 = fminf(v0 ? Dsum[nt][0] : INF, v8 ? Dsum[nt][2] : INF);
        float m1 = fminf(v0 ? Dsum[nt][1] : INF, v8 ? Dsum[nt][3] : INF);
#pragma unroll
        for (int msk = 4; msk < 32; msk <<= 1) {
            m0 = fminf(m0, __shfl_xor_sync(0xffffffffu, m0, msk));
            m1 = fminf(m1, __shfl_xor_sync(0xffffffffu, m1, msk));
        }
        if (lane < 4) {
            atomicMin((u32*)&mnS[nt * 8 + 2 * lane],     __float_as_uint(m0));
            atomicMin((u32*)&mnS[nt * 8 + 2 * lane + 1], __float_as_uint(m1));
        }
    }
    __syncthreads();
    if (tid < 64)
        atomicMin((u32*)&out[b * NN + n0 + tid], __float_as_uint(mnS[tid]));
}

extern "C" void kernel_launch(void* const* d_in, const int* in_sizes, int n_in,
                              void* d_out, int out_size) {
    (void)in_sizes; (void)n_in; (void)out_size;
    const float* x   = (const float*)d_in[0];
    const float* shp = (const float*)d_in[1];
    float* out = (float*)d_out;

    cudaFuncSetAttribute(main_kernel, cudaFuncAttributeMaxDynamicSharedMemorySize, SM_TOTAL);

    winsq_kernel<<<dim3(BB, CC), 256>>>(x, out);
    shp_prep<<<CC, NN>>>(shp);
    main_kernel<<<dim3(16, 4, BB), THREADS, SM_TOTAL>>>(x, out);
}